// round 16
// baseline (speedup 1.0000x reference)
#include <cuda_runtime.h>
#include <cuda_fp16.h>
#include <cstdint>

// ---------------- problem constants ----------------
#define B_    16
#define CIN   32
#define COUT  64
#define HO    62
#define WO    62
#define HW    4096
#define KDIM  288          // (c,g) = 32*9
#define MTOT  65536        // b*h*w pixels
#define MPAD  65800
#define MOUT  126          // output rows per CTA
#define NCTA  521
#define NSPLIT 3
#define KCPER  6           // 18 k-chunks / 3 splits

// ---------------- device scratch ----------------
__device__ __align__(16) __half g_A[(size_t)MPAD * KDIM];   // fp16 features
__device__ __align__(16) __half g_B[9 * 64 * KDIM];         // [tap][n][k] fp16

// ---------------- helpers ----------------
__device__ __forceinline__ uint32_t smem_u32(const void* p) {
    uint32_t a;
    asm("{ .reg .u64 t; cvta.to.shared.u64 t, %1; cvt.u32.u64 %0, t; }" : "=r"(a) : "l"(p));
    return a;
}
__device__ __forceinline__ void cp16(uint32_t dst, const void* src) {
    asm volatile("cp.async.cg.shared.global [%0], [%1], 16;" :: "r"(dst), "l"(src));
}
#define CP_COMMIT() asm volatile("cp.async.commit_group;" ::: "memory")
#define CP_WAIT1()  asm volatile("cp.async.wait_group 1;" ::: "memory")

#define LDSM4(r, a)                                                          \
    asm volatile("ldmatrix.sync.aligned.m8n8.x4.shared.b16 {%0,%1,%2,%3}, [%4];" \
        : "=r"((r)[0]), "=r"((r)[1]), "=r"((r)[2]), "=r"((r)[3]) : "r"(a))
#define MMA(d, a, b0, b1)                                                    \
    asm volatile("mma.sync.aligned.m16n8k16.row.col.f32.f16.f16.f32 "        \
        "{%0,%1,%2,%3}, {%4,%5,%6,%7}, {%8,%9}, {%0,%1,%2,%3};"              \
        : "+f"((d)[0]), "+f"((d)[1]), "+f"((d)[2]), "+f"((d)[3])             \
        : "r"((a)[0]), "r"((a)[1]), "r"((a)[2]), "r"((a)[3]),                \
          "r"(b0), "r"(b1))

// ---------------- kernel 0: zero the (poisoned) output ----------------
__global__ void zero_kernel(float4* __restrict__ out, int n4) {
    int i = blockIdx.x * blockDim.x + threadIdx.x;
    if (i < n4) out[i] = make_float4(0.f, 0.f, 0.f, 0.f);
}

// ---------------- kernel 1: features -> fp16 A (direct B-spline eval) -----
#define SROW 290
__global__ void __launch_bounds__(256) feat_kernel(const float* __restrict__ x) {
    __shared__ __half SA[32][SROW];
    const int m0  = blockIdx.x * 32;
    const int b   = m0 >> 12;
    const int hw0 = m0 & 4095;
    const int t   = threadIdx.x;
    const int i   = t & 31;
    const int c0  = t >> 5;

#pragma unroll
    for (int cc = 0; cc < 4; ++cc) {
        int c = c0 + cc * 8;
        float v = x[((size_t)(b * CIN + c) << 12) + hw0 + i];
        __half* row = &SA[i][c * 9];
        row[0] = __float2half(__fdividef(v, 1.0f + __expf(-v)));
#pragma unroll
        for (int g = 1; g < 9; ++g) row[g] = __ushort_as_half((unsigned short)0);
        float s = (v + 2.2f) * 2.5f;
        float fs = floorf(s);
        int idx = (int)fs;
        if (idx >= 0 && idx <= 10) {
            float u  = s - fs;
            float um = 1.0f - u;
            float u2 = u * u, u3 = u2 * u;
            const float k6 = 1.0f / 6.0f;
            float w0 = um * um * um * k6;
            float w1 = (3.0f * u3 - 6.0f * u2 + 4.0f) * k6;
            float w2 = (-3.0f * u3 + 3.0f * u2 + 3.0f * u + 1.0f) * k6;
            float w3 = u3 * k6;
            int j = idx - 3;
            if (j     >= 0 && j     <= 7) row[1 + j] = __float2half(w0);
            if (j + 1 >= 0 && j + 1 <= 7) row[2 + j] = __float2half(w1);
            if (j + 2 >= 0 && j + 2 <= 7) row[3 + j] = __float2half(w2);
            if (j + 3 >= 0 && j + 3 <= 7) row[4 + j] = __float2half(w3);
        }
    }
    __syncthreads();

#pragma unroll
    for (int u = t; u < 1152; u += 256) {
        int row = u / 36;
        int col = (u - row * 36) * 8;
        const uint32_t* pa = (const uint32_t*)&SA[row][col];
        uint4 va; va.x = pa[0]; va.y = pa[1]; va.z = pa[2]; va.w = pa[3];
        *(uint4*)&g_A[(size_t)(m0 + row) * KDIM + col] = va;
    }
}

// ---------------- kernel 2: fold weights -> fp16 ----------------
__global__ void fold_kernel(const float* __restrict__ bw,
                            const float* __restrict__ sw,
                            const float* __restrict__ ss) {
    int i = blockIdx.x * blockDim.x + threadIdx.x;    // [tap][n][k]
    if (i >= 9 * 64 * KDIM) return;
    int k = i % KDIM;
    int n = (i / KDIM) & 63;
    int p = i / (KDIM * 64);
    int c = k / 9, g = k % 9;
    int ocp = (n * CIN + c) * 9 + p;
    float val = (g == 0) ? bw[ocp] : sw[ocp * 8 + (g - 1)] * ss[ocp];
    g_B[i] = __float2half(val);
}

// ---------------- kernel 3: fp16 GEMM, swizzled, occ 3, warp-staggered ----
#define AROWS  258
#define BOFF   (AROWS * 32)              // 8256
#define BTILE  (64 * 32)                 // 2048
#define BUFSZ  (BOFF + 9 * BTILE)        // 26688
#define SMEM_TOT (2 * BUFSZ)             // 53376 -> 3 CTAs/SM

__global__ void __launch_bounds__(256, 3) gemm_kernel(float* __restrict__ out) {
    extern __shared__ __align__(16) char smem[];
    uint32_t sb = smem_u32(smem);
    const int tid  = threadIdx.x;
    const int lane = tid & 31;
    const int wid  = tid >> 5;
    const int mw = wid & 3;
    const int nw = wid >> 2;
    const int m0 = blockIdx.x * MOUT;
    const int k0 = blockIdx.y * KCPER;

    const char* Ap = (const char*)g_A;
    const char* Bp = (const char*)g_B;

    auto prefetch = [&](int kc, uint32_t bb) {
#pragma unroll
        for (int i = 0; i < 7; ++i) {
            int u = tid + i * 256;
            if (u >= 1668) break;
            const char* src;
            uint32_t dst;
            if (u < 516) {
                int row = u >> 1, half = u & 1;
                src = Ap + (size_t)(m0 + row) * (KDIM * 2) + kc * 32 + half * 16;
                dst = bb + row * 32 + ((half ^ ((row >> 2) & 1)) << 4);
            } else {
                int v = u - 516;
                int tile = v >> 7, row = (v >> 1) & 63, half = v & 1;
                src = Bp + (size_t)(tile * 64 + row) * (KDIM * 2) + kc * 32 + half * 16;
                dst = bb + BOFF + tile * BTILE + row * 32
                    + ((half ^ ((row >> 2) & 1)) << 4);
            }
            cp16(dst, src);
        }
    };

    float acc[2][4][4];
#pragma unroll
    for (int b = 0; b < 2; ++b)
#pragma unroll
        for (int c = 0; c < 4; ++c)
#pragma unroll
            for (int d = 0; d < 4; ++d) acc[b][c][d] = 0.0f;

    // --- per-thread swizzled lane offsets ---
    const int ll  = lane & 15;
    const int kh4 = lane >> 4;
    uint32_t aoff[3];
#pragma unroll
    for (int kw = 0; kw < 3; ++kw)
        aoff[kw] = (uint32_t)(ll * 32 + (((((kw + ll) >> 2) & 1) ^ kh4) << 4));
    const int lb  = (lane & 7) + ((lane >> 4) << 3);
    const int khb = (lane >> 3) & 1;
    const uint32_t boff = (uint32_t)(lb * 32 + ((((lb >> 2) & 1) ^ khb) << 4));

    // --- per-warp kh rotation (desync L1/tensor phases across warps) ---
    int khp0 = wid % 3;
    int khp1 = khp0 + 1; if (khp1 == 3) khp1 = 0;
    int khp2 = 3 - khp0 - khp1;
    uint32_t aKh[3] = { (uint32_t)(khp0 * 2048), (uint32_t)(khp1 * 2048),
                        (uint32_t)(khp2 * 2048) };
    uint32_t bKh[3] = { (uint32_t)(khp0 * 3 * BTILE), (uint32_t)(khp1 * 3 * BTILE),
                        (uint32_t)(khp2 * 3 * BTILE) };

    // double-buffered fragments
    uint32_t ah[2][2][4], bf[2][2][4];

#define LOAD_TAP(buf, s, kw) do {                                             \
        uint32_t _ab = bb + aKh[s] + (uint32_t)(((kw) + mw * 32) * 32) + aoff[kw]; \
        LDSM4(ah[buf][0], _ab);                                               \
        LDSM4(ah[buf][1], _ab + 16 * 32);                                     \
        uint32_t _bb2 = bb + BOFF + bKh[s] + (uint32_t)((kw) * BTILE)         \
                      + (uint32_t)((nw * 32) * 32) + boff;                    \
        LDSM4(bf[buf][0], _bb2);                                              \
        LDSM4(bf[buf][1], _bb2 + 16 * 32);                                    \
    } while (0)

    prefetch(k0, sb);
    CP_COMMIT();

    for (int kk = 0; kk < KCPER; ++kk) {
        if (kk < KCPER - 1) prefetch(k0 + kk + 1, sb + ((kk + 1) & 1) * BUFSZ);
        CP_COMMIT();
        CP_WAIT1();
        __syncthreads();

        const uint32_t bb = sb + (kk & 1) * BUFSZ;

        LOAD_TAP(0, 0, 0);
#pragma unroll
        for (int q = 0; q < 9; ++q) {
            const int cur = q & 1;
            if (q < 8) LOAD_TAP(cur ^ 1, (q + 1) / 3, (q + 1) % 3);
#pragma unroll
            for (int nf2 = 0; nf2 < 2; ++nf2)
#pragma unroll
                for (int hf = 0; hf < 2; ++hf)
#pragma unroll
                    for (int t2 = 0; t2 < 2; ++t2)
                        MMA(acc[t2][nf2 * 2 + hf], ah[cur][t2],
                            bf[cur][nf2][hf * 2], bf[cur][nf2][hf * 2 + 1]);
        }
        __syncthreads();
    }
#undef LOAD_TAP

    // ---- epilogue: atomic accumulate into gmem ----
    const int grp = lane >> 2;
    const int cq  = (lane & 3) * 2;
#pragma unroll
    for (int t2 = 0; t2 < 2; ++t2) {
#pragma unroll
        for (int j2 = 0; j2 < 2; ++j2) {
            int r = mw * 32 + t2 * 16 + grp + j2 * 8;
            int m = m0 + r;
            if (r < MOUT && m < MTOT) {
                int h = (m >> 6) & 63, w = m & 63, b = m >> 12;
                if (h < HO && w < WO) {
                    size_t obase = ((size_t)b * COUT) * (HO * WO) + h * WO + w;
#pragma unroll
                    for (int nf = 0; nf < 4; ++nf) {
                        int o = nw * 32 + nf * 8 + cq;
                        atomicAdd(&out[obase + (size_t)o * (HO * WO)],       acc[t2][nf][j2 * 2]);
                        atomicAdd(&out[obase + (size_t)(o + 1) * (HO * WO)], acc[t2][nf][j2 * 2 + 1]);
                    }
                }
            }
        }
    }
}

// ---------------- launch ----------------
extern "C" void kernel_launch(void* const* d_in, const int* in_sizes, int n_in,
                              void* d_out, int out_size) {
    const float* x  = (const float*)d_in[0];
    const float* bw = (const float*)d_in[1];
    const float* sw = (const float*)d_in[2];
    const float* ss = (const float*)d_in[3];
    float* out = (float*)d_out;

    static int smem_set = 0;
    if (!smem_set) {
        cudaFuncSetAttribute(gemm_kernel, cudaFuncAttributeMaxDynamicSharedMemorySize, SMEM_TOT);
        smem_set = 1;
    }

    int n4 = out_size / 4;
    zero_kernel<<<(n4 + 255) / 256, 256>>>((float4*)out, n4);
    feat_kernel<<<MTOT / 32, 256>>>(x);
    fold_kernel<<<(9 * 64 * KDIM + 255) / 256, 256>>>(bw, sw, ss);
    gemm_kernel<<<dim3(NCTA, NSPLIT), 256, SMEM_TOT>>>(out);
}

// round 17
// speedup vs baseline: 1.0448x; 1.0448x over previous
#include <cuda_runtime.h>
#include <cuda_fp16.h>
#include <cstdint>

// ---------------- problem constants ----------------
#define B_    16
#define CIN   32
#define COUT  64
#define HO    62
#define WO    62
#define HW    4096
#define KDIM  288          // (c,g) = 32*9
#define MTOT  65536        // b*h*w pixels
#define MPAD  65800
#define MOUT  126          // output rows per CTA
#define NCTA  521
#define NSPLIT 3
#define KCPER  6           // 18 k-chunks / 3 splits

// ---------------- device scratch ----------------
__device__ __align__(16) __half g_A[(size_t)MPAD * KDIM];   // fp16 features
__device__ __align__(16) __half g_B[9 * 64 * KDIM];         // [tap][n][k] fp16

// ---------------- helpers ----------------
__device__ __forceinline__ uint32_t smem_u32(const void* p) {
    uint32_t a;
    asm("{ .reg .u64 t; cvta.to.shared.u64 t, %1; cvt.u32.u64 %0, t; }" : "=r"(a) : "l"(p));
    return a;
}
__device__ __forceinline__ void cp16(uint32_t dst, const void* src) {
    asm volatile("cp.async.cg.shared.global [%0], [%1], 16;" :: "r"(dst), "l"(src));
}
#define CP_COMMIT() asm volatile("cp.async.commit_group;" ::: "memory")
#define CP_WAIT1()  asm volatile("cp.async.wait_group 1;" ::: "memory")

#define LDSM4(r, a)                                                          \
    asm volatile("ldmatrix.sync.aligned.m8n8.x4.shared.b16 {%0,%1,%2,%3}, [%4];" \
        : "=r"((r)[0]), "=r"((r)[1]), "=r"((r)[2]), "=r"((r)[3]) : "r"(a))
#define MMA(d, a, b0, b1)                                                    \
    asm volatile("mma.sync.aligned.m16n8k16.row.col.f32.f16.f16.f32 "        \
        "{%0,%1,%2,%3}, {%4,%5,%6,%7}, {%8,%9}, {%0,%1,%2,%3};"              \
        : "+f"((d)[0]), "+f"((d)[1]), "+f"((d)[2]), "+f"((d)[3])             \
        : "r"((a)[0]), "r"((a)[1]), "r"((a)[2]), "r"((a)[3]),                \
          "r"(b0), "r"(b1))

// ---------------- fused prep kernel: feat | fold | zero -------------------
// blocks [0, 2048)          : feat  (starts first — longest pole)
// blocks [2048, 2696)       : fold  (648 blocks)
// blocks [2696, 6540)       : zero  (3844 blocks)
#define PREP_FEAT  2048
#define PREP_FOLD  (PREP_FEAT + 648)
#define PREP_TOT   (PREP_FOLD + 3844)
#define SROW 290

__global__ void __launch_bounds__(256) prep_kernel(const float* __restrict__ x,
                                                   const float* __restrict__ bw,
                                                   const float* __restrict__ sw,
                                                   const float* __restrict__ ss,
                                                   float4* __restrict__ out4) {
    __shared__ __half SA[32][SROW];
    const int blk = blockIdx.x;
    const int t   = threadIdx.x;

    if (blk < PREP_FEAT) {
        // ---- feature generation: 32 pixels x 32 channels ----
        const int m0  = blk * 32;
        const int b   = m0 >> 12;
        const int hw0 = m0 & 4095;
        const int i   = t & 31;
        const int c0  = t >> 5;
#pragma unroll
        for (int cc = 0; cc < 4; ++cc) {
            int c = c0 + cc * 8;
            float v = x[((size_t)(b * CIN + c) << 12) + hw0 + i];
            __half* row = &SA[i][c * 9];
            row[0] = __float2half(__fdividef(v, 1.0f + __expf(-v)));
#pragma unroll
            for (int g = 1; g < 9; ++g) row[g] = __ushort_as_half((unsigned short)0);
            float s = (v + 2.2f) * 2.5f;
            float fs = floorf(s);
            int idx = (int)fs;
            if (idx >= 0 && idx <= 10) {
                float u  = s - fs;
                float um = 1.0f - u;
                float u2 = u * u, u3 = u2 * u;
                const float k6 = 1.0f / 6.0f;
                float w0 = um * um * um * k6;
                float w1 = (3.0f * u3 - 6.0f * u2 + 4.0f) * k6;
                float w2 = (-3.0f * u3 + 3.0f * u2 + 3.0f * u + 1.0f) * k6;
                float w3 = u3 * k6;
                int j = idx - 3;
                if (j     >= 0 && j     <= 7) row[1 + j] = __float2half(w0);
                if (j + 1 >= 0 && j + 1 <= 7) row[2 + j] = __float2half(w1);
                if (j + 2 >= 0 && j + 2 <= 7) row[3 + j] = __float2half(w2);
                if (j + 3 >= 0 && j + 3 <= 7) row[4 + j] = __float2half(w3);
            }
        }
        __syncthreads();
#pragma unroll
        for (int u = t; u < 1152; u += 256) {
            int row = u / 36;
            int col = (u - row * 36) * 8;
            const uint32_t* pa = (const uint32_t*)&SA[row][col];
            uint4 va; va.x = pa[0]; va.y = pa[1]; va.z = pa[2]; va.w = pa[3];
            *(uint4*)&g_A[(size_t)(m0 + row) * KDIM + col] = va;
        }
    } else if (blk < PREP_FOLD) {
        // ---- weight fold ----
        int i = (blk - PREP_FEAT) * 256 + t;          // [tap][n][k]
        int k = i % KDIM;
        int n = (i / KDIM) & 63;
        int p = i / (KDIM * 64);
        int c = k / 9, g = k % 9;
        int ocp = (n * CIN + c) * 9 + p;
        float val = (g == 0) ? bw[ocp] : sw[ocp * 8 + (g - 1)] * ss[ocp];
        g_B[i] = __float2half(val);
    } else {
        // ---- zero output (poisoned by harness; atomics accumulate) ----
        int i = (blk - PREP_FOLD) * 256 + t;          // exactly n4 elements
        out4[i] = make_float4(0.f, 0.f, 0.f, 0.f);
    }
}

// ---------------- gemm: fp16 mma.sync, swizzled, occ 3, split-K 3 ---------
#define AROWS  258
#define BOFF   (AROWS * 32)              // 8256
#define BTILE  (64 * 32)                 // 2048
#define BUFSZ  (BOFF + 9 * BTILE)        // 26688
#define SMEM_TOT (2 * BUFSZ)             // 53376 -> 3 CTAs/SM

__global__ void __launch_bounds__(256, 3) gemm_kernel(float* __restrict__ out) {
    extern __shared__ __align__(16) char smem[];
    uint32_t sb = smem_u32(smem);
    const int tid  = threadIdx.x;
    const int lane = tid & 31;
    const int wid  = tid >> 5;
    const int mw = wid & 3;
    const int nw = wid >> 2;
    const int m0 = blockIdx.x * MOUT;
    const int k0 = blockIdx.y * KCPER;

    const char* Ap = (const char*)g_A;
    const char* Bp = (const char*)g_B;

    auto prefetch = [&](int kc, uint32_t bb) {
#pragma unroll
        for (int i = 0; i < 7; ++i) {
            int u = tid + i * 256;
            if (u >= 1668) break;
            const char* src;
            uint32_t dst;
            if (u < 516) {
                int row = u >> 1, half = u & 1;
                src = Ap + (size_t)(m0 + row) * (KDIM * 2) + kc * 32 + half * 16;
                dst = bb + row * 32 + ((half ^ ((row >> 2) & 1)) << 4);
            } else {
                int v = u - 516;
                int tile = v >> 7, row = (v >> 1) & 63, half = v & 1;
                src = Bp + (size_t)(tile * 64 + row) * (KDIM * 2) + kc * 32 + half * 16;
                dst = bb + BOFF + tile * BTILE + row * 32
                    + ((half ^ ((row >> 2) & 1)) << 4);
            }
            cp16(dst, src);
        }
    };

    float acc[2][4][4];
#pragma unroll
    for (int b = 0; b < 2; ++b)
#pragma unroll
        for (int c = 0; c < 4; ++c)
#pragma unroll
            for (int d = 0; d < 4; ++d) acc[b][c][d] = 0.0f;

    // --- per-thread swizzled lane offsets ---
    const int ll  = lane & 15;
    const int kh4 = lane >> 4;
    uint32_t aoff[3];
#pragma unroll
    for (int kw = 0; kw < 3; ++kw)
        aoff[kw] = (uint32_t)(ll * 32 + (((((kw + ll) >> 2) & 1) ^ kh4) << 4));
    const int lb  = (lane & 7) + ((lane >> 4) << 3);
    const int khb = (lane >> 3) & 1;
    const uint32_t boff = (uint32_t)(lb * 32 + ((((lb >> 2) & 1) ^ khb) << 4));

    // double-buffered fragments
    uint32_t ah[2][2][4], bf[2][2][4];

#define LOAD_TAP(buf, kh, kw, tap) do {                                       \
        uint32_t _ab = bb + (uint32_t)(((kh) * 64 + (kw) + mw * 32) * 32) + aoff[kw]; \
        LDSM4(ah[buf][0], _ab);                                               \
        LDSM4(ah[buf][1], _ab + 16 * 32);                                     \
        uint32_t _bb2 = bb + BOFF + (uint32_t)((tap) * BTILE)                 \
                      + (uint32_t)((nw * 32) * 32) + boff;                    \
        LDSM4(bf[buf][0], _bb2);                                              \
        LDSM4(bf[buf][1], _bb2 + 16 * 32);                                    \
    } while (0)

#define MMA_TAP(buf) do {                                                     \
        _Pragma("unroll")                                                     \
        for (int nf2 = 0; nf2 < 2; ++nf2)                                     \
            _Pragma("unroll")                                                 \
            for (int hf = 0; hf < 2; ++hf)                                    \
                _Pragma("unroll")                                             \
                for (int t2 = 0; t2 < 2; ++t2)                                \
                    MMA(acc[t2][nf2 * 2 + hf], ah[buf][t2],                   \
                        bf[buf][nf2][hf * 2], bf[buf][nf2][hf * 2 + 1]);      \
    } while (0)

    prefetch(k0, sb);
    CP_COMMIT();

    for (int kk = 0; kk < KCPER; ++kk) {
        if (kk < KCPER - 1) prefetch(k0 + kk + 1, sb + ((kk + 1) & 1) * BUFSZ);
        CP_COMMIT();
        CP_WAIT1();
        __syncthreads();

        const uint32_t bb = sb + (kk & 1) * BUFSZ;

        LOAD_TAP(0, 0, 0, 0);
#pragma unroll
        for (int q = 0; q < 8; ++q) {
            const int cur = q & 1;
            const int nt = q + 1;
            LOAD_TAP(cur ^ 1, nt / 3, nt % 3, nt);
            MMA_TAP(cur);
        }
        // all chunk-kk LDSMs issued; barrier now, last tap's MMAs after —
        // next chunk's prefetch + LDSM burst overlaps them.
        __syncthreads();
        MMA_TAP(0);                      // tap 8 lives in buffer 0
    }
#undef LOAD_TAP
#undef MMA_TAP

    // ---- epilogue: atomic accumulate into gmem ----
    const int grp = lane >> 2;
    const int cq  = (lane & 3) * 2;
#pragma unroll
    for (int t2 = 0; t2 < 2; ++t2) {
#pragma unroll
        for (int j2 = 0; j2 < 2; ++j2) {
            int r = mw * 32 + t2 * 16 + grp + j2 * 8;
            int m = m0 + r;
            if (r < MOUT && m < MTOT) {
                int h = (m >> 6) & 63, w = m & 63, b = m >> 12;
                if (h < HO && w < WO) {
                    size_t obase = ((size_t)b * COUT) * (HO * WO) + h * WO + w;
#pragma unroll
                    for (int nf = 0; nf < 4; ++nf) {
                        int o = nw * 32 + nf * 8 + cq;
                        atomicAdd(&out[obase + (size_t)o * (HO * WO)],       acc[t2][nf][j2 * 2]);
                        atomicAdd(&out[obase + (size_t)(o + 1) * (HO * WO)], acc[t2][nf][j2 * 2 + 1]);
                    }
                }
            }
        }
    }
}

// ---------------- launch ----------------
extern "C" void kernel_launch(void* const* d_in, const int* in_sizes, int n_in,
                              void* d_out, int out_size) {
    const float* x  = (const float*)d_in[0];
    const float* bw = (const float*)d_in[1];
    const float* sw = (const float*)d_in[2];
    const float* ss = (const float*)d_in[3];
    float* out = (float*)d_out;

    static int smem_set = 0;
    if (!smem_set) {
        cudaFuncSetAttribute(gemm_kernel, cudaFuncAttributeMaxDynamicSharedMemorySize, SMEM_TOT);
        smem_set = 1;
    }

    prep_kernel<<<PREP_TOT, 256>>>(x, bw, sw, ss, (float4*)out);
    gemm_kernel<<<dim3(NCTA, NSPLIT), 256, SMEM_TOT>>>(out);
}